// round 16
// baseline (speedup 1.0000x reference)
#include <cuda_runtime.h>
#include <math.h>
#include <stdint.h>

#define LEV 60
#define BATCH 4096
#define NXI 4
#define NH 64
#define NMEM 64
#define NSFC 17
#define NYO 4
#define NG 256
#define NWCOL 320
#define XC 320
#define KD2 68              // padded K stride
#define TB2 16              // rows per seq CTA (2 CTAs/SM)
#define NB2 (BATCH / TB2)   // 256
#define LTB 32
#define LPB 5
#define XTB 32              // xpre tile rows
#define XGRID 296           // persistent xpre CTAs (2/SM)
#define NTILES (LEV * (BATCH / XTB))   // 7680

#define OFF_SFC (BATCH * LEV * NYO)
#define OFF_MEM (OFF_SFC + BATCH * 3)

__device__ float g_scratch[(size_t)LEV * BATCH * NH];
__device__ float g_X1[(size_t)LEV * BATCH * XC];
__device__ float g_X2[(size_t)LEV * BATCH * XC];

struct Params {
    const float *inputs_main, *inputs_aux, *rnn1_mem, *eps1, *eps2, *eps_sfc;
    const float *W_sfc, *b_sfc, *W_sfc2, *b_sfc2, *W_toa, *b_toa, *W_toa2, *b_toa2;
    const float *Wx1, *Wh1, *Wxs1, *Whs1, *Wx2, *Wh2, *Wxs2, *Whs2;
    const float *W_lat, *b_lat, *W_out, *b_out, *W_sfcout, *b_sfcout;
    const float *W_mu, *b_mu, *W_lv, *b_lv;
    float *out;
};

__device__ __forceinline__ float sigmoidf_(float x) {
    return __fdividef(1.0f, 1.0f + __expf(-x));
}
__device__ __forceinline__ float tanhf_(float x) {
    float ax = fabsf(x);
    float e  = __expf(2.0f * ax);
    float t  = 1.0f - __fdividef(2.0f, e + 1.0f);
    return copysignf(t, x);
}
__device__ __forceinline__ unsigned long long fma2_(unsigned long long a,
                                                    unsigned long long b,
                                                    unsigned long long c) {
    unsigned long long d;
    asm("fma.rn.f32x2 %0, %1, %2, %3;" : "=l"(d) : "l"(a), "l"(b), "l"(c));
    return d;
}
__device__ __forceinline__ float pairsum_(unsigned long long v) {
    float lo = __int_as_float((int)(v & 0xffffffffull));
    float hi = __int_as_float((int)(v >> 32));
    return lo + hi;
}

extern __shared__ float smem[];

// =====================================================================
// xpre_simt: X = A @ [Wa|Wb] (FFMA2), persistent, 2 CTAs/SM.
// M=32-row tiles, 256 threads, register-double-buffered A staging.
// mode 0: A = [inputs_main|rnn1_mem] at level 59-s (K=68) -> g_X1
// mode 1: A = g_scratch[s]            (K=64)              -> g_X2
// smem: W_s[320][68] + A_b[2][32][68] = 104448 B per CTA.
// =====================================================================
#define XP_A (XTB * KD2)
#define XP_SMEM ((NWCOL * KD2 + 2 * XP_A) * 4)

__device__ __forceinline__ void xpre_fetch_(int mode, int t,
                                            const float* __restrict__ im,
                                            const float* __restrict__ mem,
                                            float pref[9], int fr, int fq) {
    int s = t >> 7, b0t = (t & 127) * XTB;
    if (mode == 0) {
        size_t rowbase = ((size_t)(b0t + fr) * LEV + (LEV - 1 - s));
        const float* irow = im + rowbase * NXI;
        const float* mrow = mem + rowbase * NMEM - NXI;
#pragma unroll
        for (int j = 0; j < 9; j++) {
            int k = fq + j * 8;
            float v = 0.f;
            if (k < KD2) v = (k < NXI) ? irow[k] : mrow[k];
            pref[j] = v;
        }
    } else {
        const float* srow = g_scratch + ((size_t)s * BATCH + b0t + fr) * NH;
#pragma unroll
        for (int j = 0; j < 9; j++) {
            int k = fq + j * 8;
            pref[j] = (k < NH) ? srow[k] : 0.f;
        }
    }
}

__device__ __forceinline__ void xpre_commit_(float* __restrict__ dst,
                                             const float pref[9], int fr, int fq) {
    float* d = dst + fr * KD2;
#pragma unroll
    for (int j = 0; j < 9; j++) {
        int k = fq + j * 8;
        if (k < KD2) d[k] = pref[j];
    }
}

__global__ __launch_bounds__(256, 2)
void xpre_simt(int mode, int K, const float* __restrict__ im,
               const float* __restrict__ mem,
               const float* __restrict__ Wa, const float* __restrict__ Wb) {
    float* W_s = smem;                     // [320][KD2]
    float* A_b = smem + NWCOL * KD2;       // [2][32][KD2]
    const int tid = threadIdx.x;
    const int tx = tid & 63;
    const int ty = tid >> 6;               // 0..3, 8 rows each -> 32 rows
    const int fr = tid >> 3;               // fetch row 0..31
    const int fq = tid & 7;                // fetch k-octet
    float* Xout = mode ? g_X2 : g_X1;

    for (int idx = tid; idx < NWCOL * KD2; idx += 256) {
        int k = idx / NWCOL, j = idx % NWCOL;
        float v = 0.f;
        if (k < K) v = (j < NG) ? Wa[(size_t)k * NG + j] : Wb[(size_t)k * NH + (j - NG)];
        W_s[j * KD2 + k] = v;
    }

    const int t0 = blockIdx.x;
    float pref[9];
    xpre_fetch_(mode, t0, im, mem, pref, fr, fq);
    xpre_commit_(A_b, pref, fr, fq);
    __syncthreads();

    const float* wbase = W_s + tx * KD2;
    int buf = 0;
    for (int t = t0; t < NTILES; t += XGRID) {
        int tn = t + XGRID;
        if (tn < NTILES) xpre_fetch_(mode, tn, im, mem, pref, fr, fq);

        const float* arow = A_b + buf * XP_A + (ty * 8) * KD2;
        unsigned long long acc[8][5];
#pragma unroll
        for (int u = 0; u < 8; u++)
#pragma unroll
            for (int c = 0; c < 5; c++) acc[u][c] = 0ull;

#pragma unroll 1
        for (int kq = 0; kq < KD2 / 4; kq++) {
            ulonglong2 wv[5];
#pragma unroll
            for (int c = 0; c < 5; c++)
                wv[c] = *(const ulonglong2*)&wbase[c * (64 * KD2) + kq * 4];
#pragma unroll
            for (int u = 0; u < 8; u++) {
                ulonglong2 xv = *(const ulonglong2*)&arow[u * KD2 + kq * 4];
#pragma unroll
                for (int c = 0; c < 5; c++) {
                    acc[u][c] = fma2_(xv.x, wv[c].x, acc[u][c]);
                    acc[u][c] = fma2_(xv.y, wv[c].y, acc[u][c]);
                }
            }
        }
        {
            int s = t >> 7, b0t = (t & 127) * XTB;
            float* op = Xout + ((size_t)s * BATCH + b0t + ty * 8) * XC + tx;
#pragma unroll
            for (int u = 0; u < 8; u++)
#pragma unroll
                for (int c = 0; c < 5; c++)
                    op[u * XC + c * 64] = pairsum_(acc[u][c]);
        }
        if (tn < NTILES)
            xpre_commit_(A_b + (buf ^ 1) * XP_A, pref, fr, fq);
        __syncthreads();
        buf ^= 1;
    }
}

// =====================================================================
// Sequential h-only recurrence, K=64, TB2=16, 2 CTAs/SM.
// Register pointwise, double-buffered xh, 1 sync/step.
// =====================================================================
#define XH1 (TB2 * KD2)
#define SEQ_SMEM ((NWCOL * KD2 + 2 * XH1) * 4)

__device__ __forceinline__ void stage_Wh_(float* __restrict__ W_s,
                                          const float* __restrict__ Wh,
                                          const float* __restrict__ Whs, int tid) {
    for (int idx = tid; idx < NWCOL * KD2; idx += 256) {
        int k = idx / NWCOL, j = idx % NWCOL;
        float v = 0.f;
        if (k < NH) v = (j < NG) ? Wh[(size_t)k * NG + j] : Whs[(size_t)k * NH + (j - NG)];
        W_s[j * KD2 + k] = v;
    }
}

__device__ __forceinline__ void seq_step_(const float* __restrict__ wbase,
                                          const float* __restrict__ cur,
                                          float* __restrict__ nxt,
                                          float* __restrict__ c_reg,
                                          int tx, int ty,
                                          const float* __restrict__ xp,
                                          const float* __restrict__ ep,
                                          float* __restrict__ sp) {
    float Xr[20], ge[4];
#pragma unroll
    for (int u = 0; u < 4; u++) {
#pragma unroll
        for (int c = 0; c < 5; c++)
            Xr[u * 5 + c] = xp[u * XC + c * 64];
        ge[u] = ep[u * NH];
    }

    const float* arow = cur + (ty * 4) * KD2;
    unsigned long long acc[4][5];
#pragma unroll
    for (int u = 0; u < 4; u++)
#pragma unroll
        for (int c = 0; c < 5; c++) acc[u][c] = 0ull;
#pragma unroll 1
    for (int kq = 0; kq < 16; kq++) {
        ulonglong2 wv[5];
#pragma unroll
        for (int c = 0; c < 5; c++)
            wv[c] = *(const ulonglong2*)&wbase[c * (64 * KD2) + kq * 4];
#pragma unroll
        for (int u = 0; u < 4; u++) {
            ulonglong2 xv = *(const ulonglong2*)&arow[u * KD2 + kq * 4];
#pragma unroll
            for (int c = 0; c < 5; c++) {
                acc[u][c] = fma2_(xv.x, wv[c].x, acc[u][c]);
                acc[u][c] = fma2_(xv.y, wv[c].y, acc[u][c]);
            }
        }
    }
    float* nrow = nxt + (ty * 4) * KD2 + tx;
#pragma unroll
    for (int u = 0; u < 4; u++) {
        float iv = sigmoidf_(pairsum_(acc[u][0]) + Xr[u * 5 + 0]);
        float fv = sigmoidf_(pairsum_(acc[u][1]) + Xr[u * 5 + 1]);
        float gt = tanhf_(pairsum_(acc[u][2]) + Xr[u * 5 + 2]);
        float ov = sigmoidf_(pairsum_(acc[u][3]) + Xr[u * 5 + 3]);
        float lv = pairsum_(acc[u][4]) + Xr[u * 5 + 4];
        float cc = fv * c_reg[u] + iv * gt;
        c_reg[u] = cc;
        float h  = ov * tanhf_(cc) + ge[u] * __expf(0.5f * lv);
        nrow[u * KD2] = h;
        sp[u * NH] = h;
    }
}

__global__ __launch_bounds__(256, 2)
void rnn1_seq(Params p) {
    const int tid = threadIdx.x;
    const int b0  = blockIdx.x * TB2;
    float* W_s = smem;
    float* xh  = smem + NWCOL * KD2;
    const int tx = tid & 63, ty = tid >> 6;
    float c_reg[4];

    stage_Wh_(W_s, p.Wh1, p.Whs1, tid);
#pragma unroll
    for (int u = 0; u < 4; u++) {
        int row = ty * 4 + u;
        const float* auxrow = p.inputs_aux + (size_t)(b0 + row) * NSFC;
        float ah = p.b_sfc[tx], ac = p.b_sfc2[tx];
        for (int k = 0; k < NSFC; k++) {
            float a = auxrow[k];
            ah = fmaf(a, p.W_sfc[k * NH + tx], ah);
            ac = fmaf(a, p.W_sfc2[k * NH + tx], ac);
        }
        xh[row * KD2 + tx] = tanhf_(ah);
        c_reg[u] = tanhf_(ac);
    }
    __syncthreads();

    const float* wbase = W_s + tx * KD2;
    const float* xp = g_X1 + (size_t)(b0 + ty * 4) * XC + tx;
    const float* ep = p.eps1 + (size_t)(b0 + ty * 4) * NH + tx;
    float* sp = g_scratch + ((size_t)(LEV - 1) * BATCH + b0 + ty * 4) * NH + tx;

    for (int s = 0; s < LEV; s++) {
        const float* cur = xh + (s & 1) * XH1;
        float* nxt = xh + ((s + 1) & 1) * XH1;
        seq_step_(wbase, cur, nxt, c_reg, tx, ty, xp, ep, sp);
        xp += (size_t)BATCH * XC;
        ep += (size_t)BATCH * NH;
        sp -= (size_t)BATCH * NH;
        __syncthreads();
    }
}

__global__ __launch_bounds__(256, 2)
void rnn2_seq(Params p) {
    const int tid = threadIdx.x;
    const int b0  = blockIdx.x * TB2;
    float* W_s = smem;
    float* xh  = smem + NWCOL * KD2;
    const int tx = tid & 63, ty = tid >> 6;
    float c_reg[4];

    stage_Wh_(W_s, p.Wh2, p.Whs2, tid);
#pragma unroll
    for (int u = 0; u < 4; u++) {
        int row = ty * 4 + u;
        float x0 = p.inputs_aux[(size_t)(b0 + row) * NSFC + 1];
        float x1 = p.inputs_aux[(size_t)(b0 + row) * NSFC + 6];
        float ah = fmaf(x0, p.W_toa[tx],  fmaf(x1, p.W_toa[NH + tx],  p.b_toa[tx]));
        float ac = fmaf(x0, p.W_toa2[tx], fmaf(x1, p.W_toa2[NH + tx], p.b_toa2[tx]));
        xh[row * KD2 + tx] = tanhf_(ah);
        c_reg[u] = tanhf_(ac);
    }
    __syncthreads();

    const float* wbase = W_s + tx * KD2;
    const float* xp = g_X2 + (size_t)(b0 + ty * 4) * XC + tx;
    const float* ep = p.eps2 + (size_t)(b0 + ty * 4) * NH + tx;
    float* sp = g_scratch + (size_t)(b0 + ty * 4) * NH + tx;

    for (int s = 0; s < LEV; s++) {
        const float* cur = xh + (s & 1) * XH1;
        float* nxt = xh + ((s + 1) & 1) * XH1;
        seq_step_(wbase, cur, nxt, c_reg, tx, ty, xp, ep, sp);
        xp += (size_t)BATCH * XC;
        ep += (size_t)BATCH * NH;
        sp += (size_t)BATCH * NH;
        __syncthreads();
    }

    // surface heads from last hidden: step 59 wrote xh buffer 0
    if (tid < TB2) {
        const float* hl = xh;
        int r = tid;
        size_t b = b0 + r;
        float rad = p.b_sfcout[0];
        float mu0 = p.b_mu[0], mu1 = p.b_mu[1];
        float lv0 = p.b_lv[0], lv1 = p.b_lv[1];
        for (int k = 0; k < NH; k++) {
            float h = hl[r * KD2 + k];
            rad = fmaf(h, p.W_sfcout[k], rad);
            mu0 = fmaf(h, p.W_mu[k * 2 + 0], mu0);
            mu1 = fmaf(h, p.W_mu[k * 2 + 1], mu1);
            lv0 = fmaf(h, p.W_lv[k * 2 + 0], lv0);
            lv1 = fmaf(h, p.W_lv[k * 2 + 1], lv1);
        }
        float e0 = p.eps_sfc[b * 2 + 0], e1 = p.eps_sfc[b * 2 + 1];
        p.out[OFF_SFC + b * 3 + 0] = mu0 + e0 * __expf(0.5f * lv0);
        p.out[OFF_SFC + b * 3 + 1] = mu1 + e1 * __expf(0.5f * lv1);
        p.out[OFF_SFC + b * 3 + 2] = rad;
    }
}

// ===== latent + out heads; LPB levels per block, occ 4, fma2 =====
__global__ __launch_bounds__(256, 4)
void latent_kernel(const float* __restrict__ W_lat, const float* __restrict__ b_lat,
                   const float* __restrict__ W_out, const float* __restrict__ b_out,
                   float* __restrict__ out) {
    __shared__ float Wl[NH * KD2];
    __shared__ float wout[NH * NYO + NYO];
    __shared__ float xt[LTB * KD2];
    __shared__ float lat[LTB * KD2];

    const int l0 = blockIdx.y * LPB;
    const int b0 = blockIdx.x * LTB;
    const int tid = threadIdx.x;
    const int tx = tid & 63;
    const int ty = tid >> 6;

    for (int i = tid; i < NH * NH; i += 256) {
        int k = i >> 6, m = i & 63;
        Wl[m * KD2 + k] = W_lat[i];
    }
    for (int i = tid; i < NH * NYO; i += 256) wout[i] = W_out[i];
    if (tid < NYO) wout[NH * NYO + tid] = b_out[tid];
    float bl = b_lat[tx];

    for (int li = 0; li < LPB; li++) {
        int l = l0 + li;
        __syncthreads();
        const float* src = g_scratch + ((size_t)l * BATCH + b0) * NH;
        for (int i = tid; i < LTB * NH / 4; i += 256) {
            int r = i >> 4, q = i & 15;
            *(float4*)&xt[r * KD2 + q * 4] = *(const float4*)&src[r * NH + q * 4];
        }
        __syncthreads();

        unsigned long long accL[8];
#pragma unroll
        for (int u = 0; u < 8; u++) accL[u] = 0ull;
#pragma unroll 1
        for (int kq = 0; kq < 16; kq++) {
            ulonglong2 wv = *(const ulonglong2*)&Wl[tx * KD2 + kq * 4];
#pragma unroll
            for (int u = 0; u < 8; u++) {
                ulonglong2 xv = *(const ulonglong2*)&xt[(ty * 8 + u) * KD2 + kq * 4];
                accL[u] = fma2_(xv.x, wv.x, accL[u]);
                accL[u] = fma2_(xv.y, wv.y, accL[u]);
            }
        }
#pragma unroll
        for (int u = 0; u < 8; u++) {
            int r = ty * 8 + u;
            size_t b = b0 + r;
            float v = pairsum_(accL[u]) + bl;
            lat[r * KD2 + tx] = v;
            out[OFF_MEM + (b * LEV + l) * NMEM + tx] = v;
        }
        __syncthreads();

        if (tid < LTB * NYO) {
            int r = tid >> 2, y = tid & 3;
            float a = wout[NH * NYO + y];
            for (int m = 0; m < NH; m += 4) {
                a = fmaf(lat[r * KD2 + m + 0], wout[(m + 0) * NYO + y], a);
                a = fmaf(lat[r * KD2 + m + 1], wout[(m + 1) * NYO + y], a);
                a = fmaf(lat[r * KD2 + m + 2], wout[(m + 2) * NYO + y], a);
                a = fmaf(lat[r * KD2 + m + 3], wout[(m + 3) * NYO + y], a);
            }
            out[(size_t)(b0 + r) * (LEV * NYO) + l * NYO + y] = a;
        }
    }
}

extern "C" void kernel_launch(void* const* d_in, const int* in_sizes, int n_in,
                              void* d_out, int out_size) {
    Params p;
    p.inputs_main = (const float*)d_in[0];
    p.inputs_aux  = (const float*)d_in[1];
    p.rnn1_mem    = (const float*)d_in[2];
    p.eps1        = (const float*)d_in[3];
    p.eps2        = (const float*)d_in[4];
    p.eps_sfc     = (const float*)d_in[5];
    p.W_sfc   = (const float*)d_in[6];  p.b_sfc   = (const float*)d_in[7];
    p.W_sfc2  = (const float*)d_in[8];  p.b_sfc2  = (const float*)d_in[9];
    p.W_toa   = (const float*)d_in[10]; p.b_toa   = (const float*)d_in[11];
    p.W_toa2  = (const float*)d_in[12]; p.b_toa2  = (const float*)d_in[13];
    p.Wx1  = (const float*)d_in[14]; p.Wh1  = (const float*)d_in[15];
    p.Wxs1 = (const float*)d_in[16]; p.Whs1 = (const float*)d_in[17];
    p.Wx2  = (const float*)d_in[18]; p.Wh2  = (const float*)d_in[19];
    p.Wxs2 = (const float*)d_in[20]; p.Whs2 = (const float*)d_in[21];
    p.W_lat    = (const float*)d_in[22]; p.b_lat    = (const float*)d_in[23];
    p.W_out    = (const float*)d_in[24]; p.b_out    = (const float*)d_in[25];
    p.W_sfcout = (const float*)d_in[26]; p.b_sfcout = (const float*)d_in[27];
    p.W_mu     = (const float*)d_in[28]; p.b_mu     = (const float*)d_in[29];
    p.W_lv     = (const float*)d_in[30]; p.b_lv     = (const float*)d_in[31];
    p.out = (float*)d_out;

    cudaFuncSetAttribute(xpre_simt, cudaFuncAttributeMaxDynamicSharedMemorySize, XP_SMEM);
    cudaFuncSetAttribute(rnn1_seq,  cudaFuncAttributeMaxDynamicSharedMemorySize, SEQ_SMEM);
    cudaFuncSetAttribute(rnn2_seq,  cudaFuncAttributeMaxDynamicSharedMemorySize, SEQ_SMEM);

    xpre_simt<<<XGRID, 256, XP_SMEM>>>(0, 68, p.inputs_main, p.rnn1_mem, p.Wx1, p.Wxs1);
    rnn1_seq<<<NB2, 256, SEQ_SMEM>>>(p);
    xpre_simt<<<XGRID, 256, XP_SMEM>>>(1, 64, p.inputs_main, p.rnn1_mem, p.Wx2, p.Wxs2);
    rnn2_seq<<<NB2, 256, SEQ_SMEM>>>(p);
    latent_kernel<<<dim3(BATCH / LTB, LEV / LPB), 256>>>(p.W_lat, p.b_lat, p.W_out, p.b_out, p.out);
}

// round 17
// speedup vs baseline: 1.0787x; 1.0787x over previous
#include <cuda_runtime.h>
#include <math.h>
#include <stdint.h>

#define LEV 60
#define BATCH 4096
#define NXI 4
#define NH 64
#define NMEM 64
#define NSFC 17
#define NYO 4
#define NG 256
#define NWCOL 320
#define XC 320
#define KD2 68              // padded K stride
#define TB2 16              // rows per seq CTA (2 CTAs/SM)
#define NB2 (BATCH / TB2)   // 256
#define LTB 32
#define LPB 5
#define XTB 64              // xpre tile rows
#define NTILES (LEV * (BATCH / XTB))   // 3840

#define OFF_SFC (BATCH * LEV * NYO)
#define OFF_MEM (OFF_SFC + BATCH * 3)

__device__ float g_scratch[(size_t)LEV * BATCH * NH];
__device__ float g_X1[(size_t)LEV * BATCH * XC];
__device__ float g_X2[(size_t)LEV * BATCH * XC];

struct Params {
    const float *inputs_main, *inputs_aux, *rnn1_mem, *eps1, *eps2, *eps_sfc;
    const float *W_sfc, *b_sfc, *W_sfc2, *b_sfc2, *W_toa, *b_toa, *W_toa2, *b_toa2;
    const float *Wx1, *Wh1, *Wxs1, *Whs1, *Wx2, *Wh2, *Wxs2, *Whs2;
    const float *W_lat, *b_lat, *W_out, *b_out, *W_sfcout, *b_sfcout;
    const float *W_mu, *b_mu, *W_lv, *b_lv;
    float *out;
};

__device__ __forceinline__ float sigmoidf_(float x) {
    return __fdividef(1.0f, 1.0f + __expf(-x));
}
__device__ __forceinline__ float tanhf_(float x) {
    float ax = fabsf(x);
    float e  = __expf(2.0f * ax);
    float t  = 1.0f - __fdividef(2.0f, e + 1.0f);
    return copysignf(t, x);
}
__device__ __forceinline__ unsigned long long fma2_(unsigned long long a,
                                                    unsigned long long b,
                                                    unsigned long long c) {
    unsigned long long d;
    asm("fma.rn.f32x2 %0, %1, %2, %3;" : "=l"(d) : "l"(a), "l"(b), "l"(c));
    return d;
}
__device__ __forceinline__ float pairsum_(unsigned long long v) {
    float lo = __int_as_float((int)(v & 0xffffffffull));
    float hi = __int_as_float((int)(v >> 32));
    return lo + hi;
}
__device__ __forceinline__ uint32_t smem_u32_(const void* p) {
    uint32_t a;
    asm("{ .reg .u64 t; cvta.to.shared.u64 t, %1; cvt.u32.u64 %0, t; }" : "=r"(a) : "l"(p));
    return a;
}
__device__ __forceinline__ void cp4_(uint32_t saddr, const float* g) {
    asm volatile("cp.async.ca.shared.global [%0], [%1], 4;" :: "r"(saddr), "l"(g) : "memory");
}
#define CP_COMMIT_() asm volatile("cp.async.commit_group;" ::: "memory")
#define CP_WAIT0_()  asm volatile("cp.async.wait_group 0;" ::: "memory")
#define PAIRBAR(t)   asm volatile("bar.sync %0, 64;" :: "r"((t) + 1) : "memory")

extern __shared__ float smem[];

// =====================================================================
// xpre_simt: X = A @ [Wa|Wb] (FFMA2), persistent grid 148, 1 CTA/SM,
// M=64 tiles, A staged via cp.async double-buffer.
// mode 0: A = [inputs_main|rnn1_mem] at level 59-s (K=68) -> g_X1
// mode 1: A = g_scratch[s]            (K=64)              -> g_X2
// smem: W_s[320][68] + A_b[2][64][68] = 121856 B
// =====================================================================
#define XP_A (XTB * KD2)
#define XP_SMEM ((NWCOL * KD2 + 2 * XP_A) * 4)

__device__ __forceinline__ void xpre_stage_(int mode, int t,
                                            const float* __restrict__ im,
                                            const float* __restrict__ mem,
                                            uint32_t dstu, int fr, int fq) {
    int s = t >> 6, b0t = (t & 63) * XTB;
    uint32_t drow = dstu + (uint32_t)(fr * KD2 + fq) * 4;
    if (mode == 0) {
        size_t rowbase = ((size_t)(b0t + fr) * LEV + (LEV - 1 - s));
        const float* irow = im + rowbase * NXI;
        const float* mrow = mem + rowbase * NMEM - NXI;
#pragma unroll
        for (int j = 0; j < 9; j++) {
            int k = fq + j * 8;
            if (k < KD2) {
                const float* g = (k < NXI) ? (irow + k) : (mrow + k);
                cp4_(drow + j * 32, g);
            }
        }
    } else {
        const float* srow = g_scratch + ((size_t)s * BATCH + b0t + fr) * NH;
#pragma unroll
        for (int j = 0; j < 8; j++)
            cp4_(drow + j * 32, srow + fq + j * 8);
    }
    CP_COMMIT_();
}

__global__ __launch_bounds__(512, 1)
void xpre_simt(int mode, int K, const float* __restrict__ im,
               const float* __restrict__ mem,
               const float* __restrict__ Wa, const float* __restrict__ Wb) {
    float* W_s = smem;                     // [320][KD2]
    float* A_b = smem + NWCOL * KD2;       // [2][64][KD2]
    const int tid = threadIdx.x;
    const int tx = tid & 63;
    const int ty = tid >> 6;               // 0..7, 8 rows each
    const int fr = tid >> 3;               // fetch row 0..63
    const int fq = tid & 7;                // fetch k-octet
    float* Xout = mode ? g_X2 : g_X1;
    const uint32_t A_u = smem_u32_(A_b);

    for (int idx = tid; idx < NWCOL * KD2; idx += 512) {
        int k = idx / NWCOL, j = idx % NWCOL;
        float v = 0.f;
        if (k < K) v = (j < NG) ? Wa[(size_t)k * NG + j] : Wb[(size_t)k * NH + (j - NG)];
        W_s[j * KD2 + k] = v;
    }
    // zero both A buffers once (covers pad columns; valid cols overwritten by cp.async)
    for (int idx = tid; idx < 2 * XP_A; idx += 512) A_b[idx] = 0.f;
    __syncthreads();

    const int t0 = blockIdx.x;
    xpre_stage_(mode, t0, im, mem, A_u, fr, fq);
    CP_WAIT0_();
    __syncthreads();

    const float* wbase = W_s + tx * KD2;
    int buf = 0;
    for (int t = t0; t < NTILES; t += 148) {
        int tn = t + 148;
        if (tn < NTILES)
            xpre_stage_(mode, tn, im, mem, A_u + (uint32_t)((buf ^ 1) * XP_A) * 4, fr, fq);

        const float* arow = A_b + buf * XP_A + (ty * 8) * KD2;
        unsigned long long acc[8][5];
#pragma unroll
        for (int u = 0; u < 8; u++)
#pragma unroll
            for (int c = 0; c < 5; c++) acc[u][c] = 0ull;

#pragma unroll 1
        for (int kq = 0; kq < KD2 / 4; kq++) {
            ulonglong2 wv[5];
#pragma unroll
            for (int c = 0; c < 5; c++)
                wv[c] = *(const ulonglong2*)&wbase[c * (64 * KD2) + kq * 4];
#pragma unroll
            for (int u = 0; u < 8; u++) {
                ulonglong2 xv = *(const ulonglong2*)&arow[u * KD2 + kq * 4];
#pragma unroll
                for (int c = 0; c < 5; c++) {
                    acc[u][c] = fma2_(xv.x, wv[c].x, acc[u][c]);
                    acc[u][c] = fma2_(xv.y, wv[c].y, acc[u][c]);
                }
            }
        }
        {
            int s = t >> 6, b0t = (t & 63) * XTB;
            float* op = Xout + ((size_t)s * BATCH + b0t + ty * 8) * XC + tx;
#pragma unroll
            for (int u = 0; u < 8; u++)
#pragma unroll
                for (int c = 0; c < 5; c++)
                    op[u * XC + c * 64] = pairsum_(acc[u][c]);
        }
        if (tn < NTILES) CP_WAIT0_();
        __syncthreads();
        buf ^= 1;
    }
}

// =====================================================================
// Sequential h-only recurrence, K=64, TB2=16, 2 CTAs/SM.
// Register pointwise, double-buffered xh, PAIR-LOCAL barrier per step:
// thread (tx,ty) GEMM-reads rows ty*4..ty*4+3 written only by threads of
// the same ty group (64 threads, warps 2ty/2ty+1) -> bar.sync ty+1, 64.
// Pairs drift out of phase so MUFU-heavy pointwise overlaps other pairs' FMA.
// =====================================================================
#define XH1 (TB2 * KD2)
#define SEQ_SMEM ((NWCOL * KD2 + 2 * XH1) * 4)

__device__ __forceinline__ void stage_Wh_(float* __restrict__ W_s,
                                          const float* __restrict__ Wh,
                                          const float* __restrict__ Whs, int tid) {
    for (int idx = tid; idx < NWCOL * KD2; idx += 256) {
        int k = idx / NWCOL, j = idx % NWCOL;
        float v = 0.f;
        if (k < NH) v = (j < NG) ? Wh[(size_t)k * NG + j] : Whs[(size_t)k * NH + (j - NG)];
        W_s[j * KD2 + k] = v;
    }
}

__device__ __forceinline__ void seq_step_(const float* __restrict__ wbase,
                                          const float* __restrict__ cur,
                                          float* __restrict__ nxt,
                                          float* __restrict__ c_reg,
                                          int tx, int ty,
                                          const float* __restrict__ xp,
                                          const float* __restrict__ ep,
                                          float* __restrict__ sp) {
    float Xr[20], ge[4];
#pragma unroll
    for (int u = 0; u < 4; u++) {
#pragma unroll
        for (int c = 0; c < 5; c++)
            Xr[u * 5 + c] = xp[u * XC + c * 64];
        ge[u] = ep[u * NH];
    }

    const float* arow = cur + (ty * 4) * KD2;
    unsigned long long acc[4][5];
#pragma unroll
    for (int u = 0; u < 4; u++)
#pragma unroll
        for (int c = 0; c < 5; c++) acc[u][c] = 0ull;
#pragma unroll 1
    for (int kq = 0; kq < 16; kq++) {
        ulonglong2 wv[5];
#pragma unroll
        for (int c = 0; c < 5; c++)
            wv[c] = *(const ulonglong2*)&wbase[c * (64 * KD2) + kq * 4];
#pragma unroll
        for (int u = 0; u < 4; u++) {
            ulonglong2 xv = *(const ulonglong2*)&arow[u * KD2 + kq * 4];
#pragma unroll
            for (int c = 0; c < 5; c++) {
                acc[u][c] = fma2_(xv.x, wv[c].x, acc[u][c]);
                acc[u][c] = fma2_(xv.y, wv[c].y, acc[u][c]);
            }
        }
    }
    float* nrow = nxt + (ty * 4) * KD2 + tx;
#pragma unroll
    for (int u = 0; u < 4; u++) {
        float iv = sigmoidf_(pairsum_(acc[u][0]) + Xr[u * 5 + 0]);
        float fv = sigmoidf_(pairsum_(acc[u][1]) + Xr[u * 5 + 1]);
        float gt = tanhf_(pairsum_(acc[u][2]) + Xr[u * 5 + 2]);
        float ov = sigmoidf_(pairsum_(acc[u][3]) + Xr[u * 5 + 3]);
        float lv = pairsum_(acc[u][4]) + Xr[u * 5 + 4];
        float cc = fv * c_reg[u] + iv * gt;
        c_reg[u] = cc;
        float h  = ov * tanhf_(cc) + ge[u] * __expf(0.5f * lv);
        nrow[u * KD2] = h;
        sp[u * NH] = h;
    }
}

__global__ __launch_bounds__(256, 2)
void rnn1_seq(Params p) {
    const int tid = threadIdx.x;
    const int b0  = blockIdx.x * TB2;
    float* W_s = smem;
    float* xh  = smem + NWCOL * KD2;
    const int tx = tid & 63, ty = tid >> 6;
    float c_reg[4];

    stage_Wh_(W_s, p.Wh1, p.Whs1, tid);
#pragma unroll
    for (int u = 0; u < 4; u++) {
        int row = ty * 4 + u;
        const float* auxrow = p.inputs_aux + (size_t)(b0 + row) * NSFC;
        float ah = p.b_sfc[tx], ac = p.b_sfc2[tx];
        for (int k = 0; k < NSFC; k++) {
            float a = auxrow[k];
            ah = fmaf(a, p.W_sfc[k * NH + tx], ah);
            ac = fmaf(a, p.W_sfc2[k * NH + tx], ac);
        }
        xh[row * KD2 + tx] = tanhf_(ah);
        c_reg[u] = tanhf_(ac);
    }
    __syncthreads();

    const float* wbase = W_s + tx * KD2;
    const float* xp = g_X1 + (size_t)(b0 + ty * 4) * XC + tx;
    const float* ep = p.eps1 + (size_t)(b0 + ty * 4) * NH + tx;
    float* sp = g_scratch + ((size_t)(LEV - 1) * BATCH + b0 + ty * 4) * NH + tx;

    for (int s = 0; s < LEV; s++) {
        const float* cur = xh + (s & 1) * XH1;
        float* nxt = xh + ((s + 1) & 1) * XH1;
        seq_step_(wbase, cur, nxt, c_reg, tx, ty, xp, ep, sp);
        xp += (size_t)BATCH * XC;
        ep += (size_t)BATCH * NH;
        sp -= (size_t)BATCH * NH;
        PAIRBAR(ty);
    }
}

__global__ __launch_bounds__(256, 2)
void rnn2_seq(Params p) {
    const int tid = threadIdx.x;
    const int b0  = blockIdx.x * TB2;
    float* W_s = smem;
    float* xh  = smem + NWCOL * KD2;
    const int tx = tid & 63, ty = tid >> 6;
    float c_reg[4];

    stage_Wh_(W_s, p.Wh2, p.Whs2, tid);
#pragma unroll
    for (int u = 0; u < 4; u++) {
        int row = ty * 4 + u;
        float x0 = p.inputs_aux[(size_t)(b0 + row) * NSFC + 1];
        float x1 = p.inputs_aux[(size_t)(b0 + row) * NSFC + 6];
        float ah = fmaf(x0, p.W_toa[tx],  fmaf(x1, p.W_toa[NH + tx],  p.b_toa[tx]));
        float ac = fmaf(x0, p.W_toa2[tx], fmaf(x1, p.W_toa2[NH + tx], p.b_toa2[tx]));
        xh[row * KD2 + tx] = tanhf_(ah);
        c_reg[u] = tanhf_(ac);
    }
    __syncthreads();

    const float* wbase = W_s + tx * KD2;
    const float* xp = g_X2 + (size_t)(b0 + ty * 4) * XC + tx;
    const float* ep = p.eps2 + (size_t)(b0 + ty * 4) * NH + tx;
    float* sp = g_scratch + (size_t)(b0 + ty * 4) * NH + tx;

    for (int s = 0; s < LEV; s++) {
        const float* cur = xh + (s & 1) * XH1;
        float* nxt = xh + ((s + 1) & 1) * XH1;
        seq_step_(wbase, cur, nxt, c_reg, tx, ty, xp, ep, sp);
        xp += (size_t)BATCH * XC;
        ep += (size_t)BATCH * NH;
        sp += (size_t)BATCH * NH;
        PAIRBAR(ty);
    }
    __syncthreads();   // surface heads read all rows

    // surface heads from last hidden: step 59 wrote xh buffer 0
    if (tid < TB2) {
        const float* hl = xh;
        int r = tid;
        size_t b = b0 + r;
        float rad = p.b_sfcout[0];
        float mu0 = p.b_mu[0], mu1 = p.b_mu[1];
        float lv0 = p.b_lv[0], lv1 = p.b_lv[1];
        for (int k = 0; k < NH; k++) {
            float h = hl[r * KD2 + k];
            rad = fmaf(h, p.W_sfcout[k], rad);
            mu0 = fmaf(h, p.W_mu[k * 2 + 0], mu0);
            mu1 = fmaf(h, p.W_mu[k * 2 + 1], mu1);
            lv0 = fmaf(h, p.W_lv[k * 2 + 0], lv0);
            lv1 = fmaf(h, p.W_lv[k * 2 + 1], lv1);
        }
        float e0 = p.eps_sfc[b * 2 + 0], e1 = p.eps_sfc[b * 2 + 1];
        p.out[OFF_SFC + b * 3 + 0] = mu0 + e0 * __expf(0.5f * lv0);
        p.out[OFF_SFC + b * 3 + 1] = mu1 + e1 * __expf(0.5f * lv1);
        p.out[OFF_SFC + b * 3 + 2] = rad;
    }
}

// ===== latent + out heads; LPB levels per block, occ 4, fma2 =====
__global__ __launch_bounds__(256, 4)
void latent_kernel(const float* __restrict__ W_lat, const float* __restrict__ b_lat,
                   const float* __restrict__ W_out, const float* __restrict__ b_out,
                   float* __restrict__ out) {
    __shared__ float Wl[NH * KD2];
    __shared__ float wout[NH * NYO + NYO];
    __shared__ float xt[LTB * KD2];
    __shared__ float lat[LTB * KD2];

    const int l0 = blockIdx.y * LPB;
    const int b0 = blockIdx.x * LTB;
    const int tid = threadIdx.x;
    const int tx = tid & 63;
    const int ty = tid >> 6;

    for (int i = tid; i < NH * NH; i += 256) {
        int k = i >> 6, m = i & 63;
        Wl[m * KD2 + k] = W_lat[i];
    }
    for (int i = tid; i < NH * NYO; i += 256) wout[i] = W_out[i];
    if (tid < NYO) wout[NH * NYO + tid] = b_out[tid];
    float bl = b_lat[tx];

    for (int li = 0; li < LPB; li++) {
        int l = l0 + li;
        __syncthreads();
        const float* src = g_scratch + ((size_t)l * BATCH + b0) * NH;
        for (int i = tid; i < LTB * NH / 4; i += 256) {
            int r = i >> 4, q = i & 15;
            *(float4*)&xt[r * KD2 + q * 4] = *(const float4*)&src[r * NH + q * 4];
        }
        __syncthreads();

        unsigned long long accL[8];
#pragma unroll
        for (int u = 0; u < 8; u++) accL[u] = 0ull;
#pragma unroll 1
        for (int kq = 0; kq < 16; kq++) {
            ulonglong2 wv = *(const ulonglong2*)&Wl[tx * KD2 + kq * 4];
#pragma unroll
            for (int u = 0; u < 8; u++) {
                ulonglong2 xv = *(const ulonglong2*)&xt[(ty * 8 + u) * KD2 + kq * 4];
                accL[u] = fma2_(xv.x, wv.x, accL[u]);
                accL[u] = fma2_(xv.y, wv.y, accL[u]);
            }
        }
#pragma unroll
        for (int u = 0; u < 8; u++) {
            int r = ty * 8 + u;
            size_t b = b0 + r;
            float v = pairsum_(accL[u]) + bl;
            lat[r * KD2 + tx] = v;
            out[OFF_MEM + (b * LEV + l) * NMEM + tx] = v;
        }
        __syncthreads();

        if (tid < LTB * NYO) {
            int r = tid >> 2, y = tid & 3;
            float a = wout[NH * NYO + y];
            for (int m = 0; m < NH; m += 4) {
                a = fmaf(lat[r * KD2 + m + 0], wout[(m + 0) * NYO + y], a);
                a = fmaf(lat[r * KD2 + m + 1], wout[(m + 1) * NYO + y], a);
                a = fmaf(lat[r * KD2 + m + 2], wout[(m + 2) * NYO + y], a);
                a = fmaf(lat[r * KD2 + m + 3], wout[(m + 3) * NYO + y], a);
            }
            out[(size_t)(b0 + r) * (LEV * NYO) + l * NYO + y] = a;
        }
    }
}

extern "C" void kernel_launch(void* const* d_in, const int* in_sizes, int n_in,
                              void* d_out, int out_size) {
    Params p;
    p.inputs_main = (const float*)d_in[0];
    p.inputs_aux  = (const float*)d_in[1];
    p.rnn1_mem    = (const float*)d_in[2];
    p.eps1        = (const float*)d_in[3];
    p.eps2        = (const float*)d_in[4];
    p.eps_sfc     = (const float*)d_in[5];
    p.W_sfc   = (const float*)d_in[6];  p.b_sfc   = (const float*)d_in[7];
    p.W_sfc2  = (const float*)d_in[8];  p.b_sfc2  = (const float*)d_in[9];
    p.W_toa   = (const float*)d_in[10]; p.b_toa   = (const float*)d_in[11];
    p.W_toa2  = (const float*)d_in[12]; p.b_toa2  = (const float*)d_in[13];
    p.Wx1  = (const float*)d_in[14]; p.Wh1  = (const float*)d_in[15];
    p.Wxs1 = (const float*)d_in[16]; p.Whs1 = (const float*)d_in[17];
    p.Wx2  = (const float*)d_in[18]; p.Wh2  = (const float*)d_in[19];
    p.Wxs2 = (const float*)d_in[20]; p.Whs2 = (const float*)d_in[21];
    p.W_lat    = (const float*)d_in[22]; p.b_lat    = (const float*)d_in[23];
    p.W_out    = (const float*)d_in[24]; p.b_out    = (const float*)d_in[25];
    p.W_sfcout = (const float*)d_in[26]; p.b_sfcout = (const float*)d_in[27];
    p.W_mu     = (const float*)d_in[28]; p.b_mu     = (const float*)d_in[29];
    p.W_lv     = (const float*)d_in[30]; p.b_lv     = (const float*)d_in[31];
    p.out = (float*)d_out;

    cudaFuncSetAttribute(xpre_simt, cudaFuncAttributeMaxDynamicSharedMemorySize, XP_SMEM);
    cudaFuncSetAttribute(rnn1_seq,  cudaFuncAttributeMaxDynamicSharedMemorySize, SEQ_SMEM);
    cudaFuncSetAttribute(rnn2_seq,  cudaFuncAttributeMaxDynamicSharedMemorySize, SEQ_SMEM);

    xpre_simt<<<148, 512, XP_SMEM>>>(0, 68, p.inputs_main, p.rnn1_mem, p.Wx1, p.Wxs1);
    rnn1_seq<<<NB2, 256, SEQ_SMEM>>>(p);
    xpre_simt<<<148, 512, XP_SMEM>>>(1, 64, p.inputs_main, p.rnn1_mem, p.Wx2, p.Wxs2);
    rnn2_seq<<<NB2, 256, SEQ_SMEM>>>(p);
    latent_kernel<<<dim3(BATCH / LTB, LEV / LPB), 256>>>(p.W_lat, p.b_lat, p.W_out, p.b_out, p.out);
}